// round 11
// baseline (speedup 1.0000x reference)
#include <cuda_runtime.h>
#include <cstdint>

#define BATCH  8192
#define SEQ    100
#define EMBED  50
#define HID    20
#define NLABEL 15
#define VOCAB  50000

// Precomputed P[v][64] = rearranged(emb_table[v] @ W1 + bi1), owner-major:
// owner q (0..3) gets 16 slots: [0..4]=z cols q*5.., [5..9]=r, [10..14]=h, [15]=pad
__device__ float g_P[VOCAB * 64];

// ---------------- helpers ----------------
__device__ __forceinline__ unsigned long long fma2(unsigned long long a,
                                                   unsigned long long b,
                                                   unsigned long long c) {
    unsigned long long d;
    asm("fma.rn.f32x2 %0, %1, %2, %3;" : "=l"(d) : "l"(a), "l"(b), "l"(c));
    return d;
}
__device__ __forceinline__ unsigned long long add2(unsigned long long a,
                                                   unsigned long long b) {
    unsigned long long d;
    asm("add.rn.f32x2 %0, %1, %2;" : "=l"(d) : "l"(a), "l"(b));
    return d;
}
__device__ __forceinline__ unsigned long long pack2(float f) {
    unsigned long long r;
    unsigned int u = __float_as_uint(f);
    asm("mov.b64 %0, {%1, %1};" : "=l"(r) : "r"(u));
    return r;
}
__device__ __forceinline__ float2 unpack2(unsigned long long v) {
    float2 r;
    asm("mov.b64 {%0, %1}, %2;" : "=f"(r.x), "=f"(r.y) : "l"(v));
    return r;
}
__device__ __forceinline__ float tanha(float x) {
    float y;
    asm("tanh.approx.f32 %0, %1;" : "=f"(y) : "f"(x));
    return y;
}
__device__ __forceinline__ unsigned long long shfl_xor4_u64(unsigned long long v) {
    unsigned int lo = (unsigned int)v, hi = (unsigned int)(v >> 32);
    lo = __shfl_xor_sync(0xFFFFFFFFu, lo, 4);
    hi = __shfl_xor_sync(0xFFFFFFFFu, hi, 4);
    return ((unsigned long long)hi << 32) | lo;
}
// rearranged slot index (0..63) -> original gate column (0..59), or -1 pad
__device__ __forceinline__ int remap_col(int j64) {
    int q = j64 >> 4;
    int jj = j64 & 15;
    if (jj >= 15) return -1;
    int g = jj / 5;
    int l = jj - g * 5;
    return g * HID + q * 5 + l;
}

// ---------------- P precompute ----------------
#define VPB 64
__global__ void __launch_bounds__(256) prep_P_kernel(const float* __restrict__ emb,
                                                     const float* __restrict__ W1,
                                                     const float* __restrict__ b1) {
    __shared__ __align__(16) float W1r[EMBED][64];
    __shared__ float biasr[64];
    __shared__ float embs[VPB][EMBED];
    int tid = threadIdx.x;
    for (int d = tid; d < EMBED * 64; d += 256) {
        int k = d >> 6, j = d & 63;
        int src = remap_col(j);
        W1r[k][j] = (src >= 0) ? W1[k * (3 * HID) + src] : 0.0f;
    }
    if (tid < 64) {
        int src = remap_col(tid);
        biasr[tid] = (src >= 0) ? b1[src] : 0.0f;
    }
    int v0 = blockIdx.x * VPB;
    for (int i = tid; i < VPB * EMBED; i += 256) {
        int vv = i / EMBED, k = i - vv * EMBED;
        int v = v0 + vv;
        embs[vv][k] = (v < VOCAB) ? emb[v * EMBED + k] : 0.0f;
    }
    __syncthreads();
    int d = tid & 63;
    int vbase = tid >> 6;
    #pragma unroll
    for (int i = 0; i < 16; i++) {
        int vl = vbase + 4 * i;
        int v = v0 + vl;
        if (v >= VOCAB) continue;
        float acc = biasr[d];
        #pragma unroll
        for (int k = 0; k < EMBED; k++)
            acc = fmaf(embs[vl][k], W1r[k][d], acc);
        g_P[v * 64 + d] = acc;
    }
}

// ---------------- main fused GRU kernel ----------------
// 8 threads per row-pair: thread (q, s). q = owner of hidden indices
// q*5..q*5+4 (all 3 gates) for BOTH rows; s = k-half (k in [10s,10s+10)).
// After the half-k matvec, partner halves merge via shfl.xor(4); thread s
// finalizes row (a if s==0 else b): gate math + h writeback + P gather.
//
// sW layout (floats): [k][mat][j][q][4] -> per-k stride = 192 floats
//                     = 48 ulonglong2; per-mat stride = 64 floats = 16 u2.
#define RPB     56
#define PPB     28          // row-pairs per block
#define BLOCK   224         // 28 * 8
#define HSTRIDE 21
#define K_U2    48          // ulonglong2 per k-slice of sW
#define MAT_U2  16          // ulonglong2 per matrix within a k-slice

__global__ void __launch_bounds__(BLOCK) gru_main_kernel(
    const int*   __restrict__ x,
    const float* __restrict__ U1,
    const float* __restrict__ b1,
    const float* __restrict__ W2,
    const float* __restrict__ U2,
    const float* __restrict__ b2,
    const float* __restrict__ Wd,
    const float* __restrict__ bd,
    float*       __restrict__ out) {

    __shared__ __align__(16) float sW[HID * 192];   // [k][mat][j][q][4]
    __shared__ __align__(16) float sbr1[64];
    __shared__ __align__(16) float sbi2[64];
    __shared__ __align__(16) float sbr2[64];
    __shared__ __align__(16) float sWd[HID * 16];
    __shared__ float sbd[16];
    __shared__ __align__(16) float sh1[RPB * HSTRIDE];
    __shared__ __align__(16) float sh2[RPB * HSTRIDE];

    int tid = threadIdx.x;

    // ---- stage interleaved weights ----
    for (int d = tid; d < HID * 192; d += BLOCK) {
        int k   = d / 192;
        int rem = d - k * 192;
        int mat = rem >> 6;
        int s64 = rem & 63;            // (j*4+q)*4+c
        int j   = s64 >> 4;
        int q_  = (s64 >> 2) & 3;
        int c   = s64 & 3;
        int jj  = j * 4 + c;
        int src = remap_col(q_ * 16 + jj);
        float v = 0.0f;
        if (src >= 0) {
            int idx = k * (3 * HID) + src;
            v = (mat == 0) ? U1[idx] : (mat == 1) ? W2[idx] : U2[idx];
        }
        sW[d] = v;
    }
    if (tid < 64) {
        int src = remap_col(tid);
        float a = 0.0f, bb = 0.0f, c = 0.0f;
        if (src >= 0) {
            a  = b1[3 * HID + src];
            bb = b2[src];
            c  = b2[3 * HID + src];
        }
        sbr1[tid] = a; sbi2[tid] = bb; sbr2[tid] = c;
    }
    for (int d = tid; d < HID * 16; d += BLOCK) {
        int k = d >> 4, j = d & 15;
        sWd[d] = (j < NLABEL) ? Wd[k * NLABEL + j] : 0.0f;
    }
    if (tid < 16) sbd[tid] = (tid < NLABEL) ? bd[tid] : 0.0f;
    __syncthreads();

    int rp = tid >> 3;            // row-pair 0..27
    int s  = (tid >> 2) & 1;      // k-half & finalized row
    int q  = tid & 3;             // owner
    int rowa  = blockIdx.x * RPB + rp * 2;
    if (rowa >= BATCH) return;    // whole 8-lane group exits together
    int myrow = rowa + s;

    int lane = tid & 31;
    unsigned gmask = 0xFFu << (lane & ~7);

    float* ph1a = sh1 + (rp * 2) * HSTRIDE;
    float* ph1b = ph1a + HSTRIDE;
    float* ph2a = sh2 + (rp * 2) * HSTRIDE;
    float* ph2b = ph2a + HSTRIDE;
    float* ph1m = s ? ph1b : ph1a;     // my finalized row
    float* ph2m = s ? ph2b : ph2a;

    const float* ph1ak = ph1a + s * 10;    // k-half bases
    const float* ph1bk = ph1b + s * 10;
    const float* ph2ak = ph2a + s * 10;
    const float* ph2bk = ph2b + s * 10;

    const int* xm = x + (size_t)myrow * SEQ;

    const ulonglong2* br1v = reinterpret_cast<const ulonglong2*>(sbr1) + q * 4;
    const ulonglong2* bi2v = reinterpret_cast<const ulonglong2*>(sbi2) + q * 4;
    const ulonglong2* br2v = reinterpret_cast<const ulonglong2*>(sbr2) + q * 4;

    float h1o[5], h2o[5];
    #pragma unroll
    for (int i = 0; i < 5; i++) {
        h1o[i] = 0.f; h2o[i] = 0.f;
        ph2m[q * 5 + i] = 0.f;          // GRU2 state starts at 0
    }

    // -------- prologue: GRU1(0) for my row (h1 = 0 -> mh = br1) --------
    int tok = xm[0];
    {
        const float4* pp = reinterpret_cast<const float4*>(g_P + (size_t)tok * 64 + q * 16);
        float4 p0 = pp[0], p1 = pp[1], p2 = pp[2], p3 = pp[3];
        float px[16] = {p0.x,p0.y,p0.z,p0.w, p1.x,p1.y,p1.z,p1.w,
                        p2.x,p2.y,p2.z,p2.w, p3.x,p3.y,p3.z,p3.w};
        #pragma unroll
        for (int i = 0; i < 5; i++) {
            float c0 = sbr1[q * 16 + i];
            float c1 = sbr1[q * 16 + 5 + i];
            float c2 = sbr1[q * 16 + 10 + i];
            float zt = tanha(0.5f * (px[i] + c0));
            float r  = 0.5f + 0.5f * tanha(0.5f * (px[5 + i] + c1));
            float hh = tanha(px[10 + i] + r * c2);
            h1o[i] = 0.5f * hh - 0.5f * zt * hh;
            ph1m[q * 5 + i] = h1o[i];
        }
        __syncwarp(gmask);
    }

    int tok_n = xm[1];

    // -------- main loop: iteration t does GRU2(t) and GRU1(t+1) --------
    for (int t = 0; t < SEQ - 1; t++) {
        // prefetch input projection for GRU1(t+1), my row only
        const float4* pp = reinterpret_cast<const float4*>(g_P + (size_t)tok_n * 64 + q * 16);
        float4 p0 = pp[0], p1 = pp[1], p2 = pp[2], p3 = pp[3];
        int t2 = t + 2;
        tok_n = xm[(t2 < SEQ) ? t2 : (SEQ - 1)];

        unsigned long long Aa[8], Ab[8], Xa[8], Xb[8], Ha[8], Hb[8];
        #pragma unroll
        for (int j = 0; j < 4; j++) {
            // bias only in half s==0 (merge adds the two halves)
            ulonglong2 ta = br1v[j];
            unsigned long long bz0 = s ? 0ull : ta.x;
            unsigned long long bz1 = s ? 0ull : ta.y;
            Aa[2*j] = bz0; Aa[2*j+1] = bz1; Ab[2*j] = bz0; Ab[2*j+1] = bz1;
            ulonglong2 tx = bi2v[j];
            bz0 = s ? 0ull : tx.x; bz1 = s ? 0ull : tx.y;
            Xa[2*j] = bz0; Xa[2*j+1] = bz1; Xb[2*j] = bz0; Xb[2*j+1] = bz1;
            ulonglong2 th = br2v[j];
            bz0 = s ? 0ull : th.x; bz1 = s ? 0ull : th.y;
            Ha[2*j] = bz0; Ha[2*j+1] = bz1; Hb[2*j] = bz0; Hb[2*j+1] = bz1;
        }
        const ulonglong2* wbase =
            reinterpret_cast<const ulonglong2*>(sW) + (size_t)s * 10 * K_U2;
        #pragma unroll
        for (int k = 0; k < 10; k++) {
            unsigned long long h1ap = pack2(ph1ak[k]);
            unsigned long long h1bp = pack2(ph1bk[k]);
            unsigned long long h2ap = pack2(ph2ak[k]);
            unsigned long long h2bp = pack2(ph2bk[k]);
            const ulonglong2* wk = wbase + k * K_U2;
            #pragma unroll
            for (int j = 0; j < 4; j++) {
                ulonglong2 w0 = wk[0 * MAT_U2 + j * 4 + q];   // U1
                Aa[2*j]   = fma2(w0.x, h1ap, Aa[2*j]);
                Aa[2*j+1] = fma2(w0.y, h1ap, Aa[2*j+1]);
                Ab[2*j]   = fma2(w0.x, h1bp, Ab[2*j]);
                Ab[2*j+1] = fma2(w0.y, h1bp, Ab[2*j+1]);
                ulonglong2 w1 = wk[1 * MAT_U2 + j * 4 + q];   // W2
                Xa[2*j]   = fma2(w1.x, h1ap, Xa[2*j]);
                Xa[2*j+1] = fma2(w1.y, h1ap, Xa[2*j+1]);
                Xb[2*j]   = fma2(w1.x, h1bp, Xb[2*j]);
                Xb[2*j+1] = fma2(w1.y, h1bp, Xb[2*j+1]);
                ulonglong2 w2 = wk[2 * MAT_U2 + j * 4 + q];   // U2
                Ha[2*j]   = fma2(w2.x, h2ap, Ha[2*j]);
                Ha[2*j+1] = fma2(w2.y, h2ap, Ha[2*j+1]);
                Hb[2*j]   = fma2(w2.x, h2bp, Hb[2*j]);
                Hb[2*j+1] = fma2(w2.y, h2bp, Hb[2*j+1]);
            }
        }

        // ---- merge halves: thread s finalizes row (s ? b : a) ----
        unsigned long long FA[8], FX[8], FH[8];
        #pragma unroll
        for (int j = 0; j < 8; j++) {
            unsigned long long give = s ? Aa[j] : Ab[j];
            unsigned long long mine = s ? Ab[j] : Aa[j];
            FA[j] = add2(mine, shfl_xor4_u64(give));
            give = s ? Xa[j] : Xb[j];
            mine = s ? Xb[j] : Xa[j];
            FX[j] = add2(mine, shfl_xor4_u64(give));
            give = s ? Ha[j] : Hb[j];
            mine = s ? Hb[j] : Ha[j];
            FH[j] = add2(mine, shfl_xor4_u64(give));
        }

        float a[16], bx[16], bh[16];
        #pragma unroll
        for (int j = 0; j < 8; j++) {
            float2 fa = unpack2(FA[j]); a[2*j]  = fa.x; a[2*j+1]  = fa.y;
            float2 fx = unpack2(FX[j]); bx[2*j] = fx.x; bx[2*j+1] = fx.y;
            float2 fh = unpack2(FH[j]); bh[2*j] = fh.x; bh[2*j+1] = fh.y;
        }
        float px[16] = {p0.x,p0.y,p0.z,p0.w, p1.x,p1.y,p1.z,p1.w,
                        p2.x,p2.y,p2.z,p2.w, p3.x,p3.y,p3.z,p3.w};

        // GRU2(t) gates (my row)
        #pragma unroll
        for (int i = 0; i < 5; i++) {
            float zt = tanha(0.5f * (bx[i] + bh[i]));
            float r  = 0.5f + 0.5f * tanha(0.5f * (bx[5+i] + bh[5+i]));
            float hh = tanha(bx[10+i] + r * bh[10+i]);
            float ho = h2o[i];
            h2o[i] = 0.5f * (ho + hh) + 0.5f * zt * (ho - hh);
        }
        // GRU1(t+1) gates (my row)
        #pragma unroll
        for (int i = 0; i < 5; i++) {
            float zt = tanha(0.5f * (px[i] + a[i]));
            float r  = 0.5f + 0.5f * tanha(0.5f * (px[5+i] + a[5+i]));
            float hh = tanha(px[10+i] + r * a[10+i]);
            float ho = h1o[i];
            h1o[i] = 0.5f * (ho + hh) + 0.5f * zt * (ho - hh);
        }

        __syncwarp(gmask);   // group reads of old h done
        #pragma unroll
        for (int i = 0; i < 5; i++) {
            ph1m[q * 5 + i] = h1o[i];
            ph2m[q * 5 + i] = h2o[i];
        }
        __syncwarp(gmask);   // new h visible to group
    }

    // -------- epilogue: GRU2(SEQ-1) --------
    {
        unsigned long long Xa[8], Xb[8], Ha[8], Hb[8];
        #pragma unroll
        for (int j = 0; j < 4; j++) {
            ulonglong2 tx = bi2v[j];
            unsigned long long bz0 = s ? 0ull : tx.x;
            unsigned long long bz1 = s ? 0ull : tx.y;
            Xa[2*j] = bz0; Xa[2*j+1] = bz1; Xb[2*j] = bz0; Xb[2*j+1] = bz1;
            ulonglong2 th = br2v[j];
            bz0 = s ? 0ull : th.x; bz1 = s ? 0ull : th.y;
            Ha[2*j] = bz0; Ha[2*j+1] = bz1; Hb[2*j] = bz0; Hb[2*j+1] = bz1;
        }
        const ulonglong2* wbase =
            reinterpret_cast<const ulonglong2*>(sW) + (size_t)s * 10 * K_U2;
        #pragma unroll
        for (int k = 0; k < 10; k++) {
            unsigned long long h1ap = pack2(ph1ak[k]);
            unsigned long long h1bp = pack2(ph1bk[k]);
            unsigned long long h2ap = pack2(ph2ak[k]);
            unsigned long long h2bp = pack2(ph2bk[k]);
            const ulonglong2* wk = wbase + k * K_U2;
            #pragma unroll
            for (int j = 0; j < 4; j++) {
                ulonglong2 w1 = wk[1 * MAT_U2 + j * 4 + q];
                Xa[2*j]   = fma2(w1.x, h1ap, Xa[2*j]);
                Xa[2*j+1] = fma2(w1.y, h1ap, Xa[2*j+1]);
                Xb[2*j]   = fma2(w1.x, h1bp, Xb[2*j]);
                Xb[2*j+1] = fma2(w1.y, h1bp, Xb[2*j+1]);
                ulonglong2 w2 = wk[2 * MAT_U2 + j * 4 + q];
                Ha[2*j]   = fma2(w2.x, h2ap, Ha[2*j]);
                Ha[2*j+1] = fma2(w2.y, h2ap, Ha[2*j+1]);
                Hb[2*j]   = fma2(w2.x, h2bp, Hb[2*j]);
                Hb[2*j+1] = fma2(w2.y, h2bp, Hb[2*j+1]);
            }
        }
        unsigned long long FX[8], FH[8];
        #pragma unroll
        for (int j = 0; j < 8; j++) {
            unsigned long long give = s ? Xa[j] : Xb[j];
            unsigned long long mine = s ? Xb[j] : Xa[j];
            FX[j] = add2(mine, shfl_xor4_u64(give));
            give = s ? Ha[j] : Hb[j];
            mine = s ? Hb[j] : Ha[j];
            FH[j] = add2(mine, shfl_xor4_u64(give));
        }
        float bx[16], bh[16];
        #pragma unroll
        for (int j = 0; j < 8; j++) {
            float2 fx = unpack2(FX[j]); bx[2*j] = fx.x; bx[2*j+1] = fx.y;
            float2 fh = unpack2(FH[j]); bh[2*j] = fh.x; bh[2*j+1] = fh.y;
        }
        #pragma unroll
        for (int i = 0; i < 5; i++) {
            float zt = tanha(0.5f * (bx[i] + bh[i]));
            float r  = 0.5f + 0.5f * tanha(0.5f * (bx[5+i] + bh[5+i]));
            float hh = tanha(bx[10+i] + r * bh[10+i]);
            float ho = h2o[i];
            h2o[i] = 0.5f * (ho + hh) + 0.5f * zt * (ho - hh);
        }
        __syncwarp(gmask);
        #pragma unroll
        for (int i = 0; i < 5; i++)
            ph2m[q * 5 + i] = h2o[i];
        __syncwarp(gmask);
    }

    // -------- dense head (my row, cols q*4..q*4+3) --------
    {
        float hv[HID];
        #pragma unroll
        for (int k = 0; k < HID; k++) hv[k] = ph2m[k];
        #pragma unroll
        for (int c = 0; c < 4; c++) {
            int col = q * 4 + c;
            if (col >= NLABEL) break;
            float acc = sbd[col];
            #pragma unroll
            for (int k = 0; k < HID; k++)
                acc = fmaf(hv[k], sWd[k * 16 + col], acc);
            out[(size_t)myrow * NLABEL + col] = acc;
        }
    }
}

// ---------------- launch ----------------
extern "C" void kernel_launch(void* const* d_in, const int* in_sizes, int n_in,
                              void* d_out, int out_size) {
    const int*   x    = (const int*)  d_in[0];
    const float* emb  = (const float*)d_in[1];
    const float* W1   = (const float*)d_in[2];
    const float* U1   = (const float*)d_in[3];
    const float* b1   = (const float*)d_in[4];
    const float* W2   = (const float*)d_in[5];
    const float* U2   = (const float*)d_in[6];
    const float* b2   = (const float*)d_in[7];
    const float* Wd   = (const float*)d_in[8];
    const float* bd   = (const float*)d_in[9];
    float* out = (float*)d_out;

    prep_P_kernel<<<(VOCAB + VPB - 1) / VPB, 256>>>(emb, W1, b1);
    gru_main_kernel<<<(BATCH + RPB - 1) / RPB, BLOCK>>>(x, U1, b1, W2, U2, b2, Wd, bd, out);
}

// round 12
// speedup vs baseline: 1.0708x; 1.0708x over previous
#include <cuda_runtime.h>
#include <cstdint>

#define BATCH  8192
#define SEQ    100
#define EMBED  50
#define HID    20
#define NLABEL 15
#define VOCAB  50000

// Precomputed P[v][64] = rearranged(emb_table[v] @ W1 + bi1), owner-major:
// owner q (0..3) gets 16 slots: [0..4]=z cols q*5.., [5..9]=r, [10..14]=h, [15]=pad
__device__ float g_P[VOCAB * 64];

// ---------------- helpers ----------------
__device__ __forceinline__ unsigned long long fma2(unsigned long long a,
                                                   unsigned long long b,
                                                   unsigned long long c) {
    unsigned long long d;
    asm("fma.rn.f32x2 %0, %1, %2, %3;" : "=l"(d) : "l"(a), "l"(b), "l"(c));
    return d;
}
__device__ __forceinline__ unsigned long long pack2(float f) {
    unsigned long long r;
    unsigned int u = __float_as_uint(f);
    asm("mov.b64 %0, {%1, %1};" : "=l"(r) : "r"(u));
    return r;
}
__device__ __forceinline__ float2 unpack2(unsigned long long v) {
    float2 r;
    asm("mov.b64 {%0, %1}, %2;" : "=f"(r.x), "=f"(r.y) : "l"(v));
    return r;
}
__device__ __forceinline__ float tanha(float x) {
    float y;
    asm("tanh.approx.f32 %0, %1;" : "=f"(y) : "f"(x));
    return y;
}
// rearranged slot index (0..63) -> original gate column (0..59), or -1 pad
__device__ __forceinline__ int remap_col(int j64) {
    int q = j64 >> 4;
    int jj = j64 & 15;
    if (jj >= 15) return -1;
    int g = jj / 5;
    int l = jj - g * 5;
    return g * HID + q * 5 + l;
}
// GRU gate update: xp = input-side 16 preacts, hp = recurrent-side 16 preacts,
// ho[5] updated in place.  z,r,h gate order; reset_after semantics.
__device__ __forceinline__ void gru_gates(const float* xp, const float* hp, float* ho) {
    #pragma unroll
    for (int i = 0; i < 5; i++) {
        float zt = tanha(0.5f * (xp[i] + hp[i]));
        float r  = 0.5f + 0.5f * tanha(0.5f * (xp[5 + i] + hp[5 + i]));
        float hh = tanha(xp[10 + i] + r * hp[10 + i]);
        float o  = ho[i];
        ho[i] = 0.5f * (o + hh) + 0.5f * zt * (o - hh);
    }
}

// ---------------- P precompute ----------------
#define VPB 64
__global__ void __launch_bounds__(256) prep_P_kernel(const float* __restrict__ emb,
                                                     const float* __restrict__ W1,
                                                     const float* __restrict__ b1) {
    __shared__ __align__(16) float W1r[EMBED][64];
    __shared__ float biasr[64];
    __shared__ float embs[VPB][EMBED];
    int tid = threadIdx.x;
    for (int d = tid; d < EMBED * 64; d += 256) {
        int k = d >> 6, j = d & 63;
        int src = remap_col(j);
        W1r[k][j] = (src >= 0) ? W1[k * (3 * HID) + src] : 0.0f;
    }
    if (tid < 64) {
        int src = remap_col(tid);
        biasr[tid] = (src >= 0) ? b1[src] : 0.0f;
    }
    int v0 = blockIdx.x * VPB;
    for (int i = tid; i < VPB * EMBED; i += 256) {
        int vv = i / EMBED, k = i - vv * EMBED;
        int v = v0 + vv;
        embs[vv][k] = (v < VOCAB) ? emb[v * EMBED + k] : 0.0f;
    }
    __syncthreads();
    int d = tid & 63;
    int vbase = tid >> 6;
    #pragma unroll
    for (int i = 0; i < 16; i++) {
        int vl = vbase + 4 * i;
        int v = v0 + vl;
        if (v >= VOCAB) continue;
        float acc = biasr[d];
        #pragma unroll
        for (int k = 0; k < EMBED; k++)
            acc = fmaf(embs[vl][k], W1r[k][d], acc);
        g_P[v * 64 + d] = acc;
    }
}

// ---------------- main fused GRU kernel ----------------
// 4 owner-lanes (q) x 3 rows per thread.  Thread q owns hidden indices
// q*5..q*5+4 (all 3 gates) of its 3 rows; every weight load is reused 3x.
// Three sequential k-passes per step keep peak accumulators at 48 u64:
//   pass A (U1, h1-old) -> GRU1 gates -> pass X (W2, h1-old)
//   -> pass H (U2, h2-old) -> GRU2 gates -> h writeback.
// sW layout (floats): [k][mat][j][q][4]; per-k = 48 u2; U1/W2/U2 at +0/+16/+32.
#define RPB     57
#define BLOCK   76          // 19 triples * 4 lanes
#define HSTRIDE 21
#define K_U2    48
#define NROW    3

__global__ void __launch_bounds__(BLOCK) gru_main_kernel(
    const int*   __restrict__ x,
    const float* __restrict__ U1,
    const float* __restrict__ b1,
    const float* __restrict__ W2,
    const float* __restrict__ U2,
    const float* __restrict__ b2,
    const float* __restrict__ Wd,
    const float* __restrict__ bd,
    float*       __restrict__ out) {

    __shared__ __align__(16) float sW[HID * 192];
    __shared__ __align__(16) float sbr1[64];
    __shared__ __align__(16) float sbi2[64];
    __shared__ __align__(16) float sbr2[64];
    __shared__ __align__(16) float sWd[HID * 16];
    __shared__ float sbd[16];
    __shared__ __align__(16) float sh1[RPB * HSTRIDE];
    __shared__ __align__(16) float sh2[RPB * HSTRIDE];

    int tid = threadIdx.x;

    // ---- stage interleaved weights (same layout as validated R7) ----
    for (int d = tid; d < HID * 192; d += BLOCK) {
        int k   = d / 192;
        int rem = d - k * 192;
        int mat = rem >> 6;
        int s64 = rem & 63;            // (j*4+q)*4+c
        int j   = s64 >> 4;
        int q_  = (s64 >> 2) & 3;
        int c   = s64 & 3;
        int jj  = j * 4 + c;
        int src = remap_col(q_ * 16 + jj);
        float v = 0.0f;
        if (src >= 0) {
            int idx = k * (3 * HID) + src;
            v = (mat == 0) ? U1[idx] : (mat == 1) ? W2[idx] : U2[idx];
        }
        sW[d] = v;
    }
    if (tid < 64) {
        int src = remap_col(tid);
        float a = 0.0f, bb = 0.0f, c = 0.0f;
        if (src >= 0) {
            a  = b1[3 * HID + src];
            bb = b2[src];
            c  = b2[3 * HID + src];
        }
        sbr1[tid] = a; sbi2[tid] = bb; sbr2[tid] = c;
    }
    for (int d = tid; d < HID * 16; d += BLOCK) {
        int k = d >> 4, j = d & 15;
        sWd[d] = (j < NLABEL) ? Wd[k * NLABEL + j] : 0.0f;
    }
    if (tid < 16) sbd[tid] = (tid < NLABEL) ? bd[tid] : 0.0f;
    __syncthreads();

    int tp = tid >> 2;            // triple index 0..18
    int q  = tid & 3;             // owner lane
    int lane = tid & 31;
    unsigned gmask = 0xFu << (lane & ~3);

    int row0 = blockIdx.x * RPB + tp * NROW;

    float* ph1[NROW];
    float* ph2[NROW];
    const int* xr[NROW];
    int rowv[NROW];
    #pragma unroll
    for (int r = 0; r < NROW; r++) {
        int rl = tp * NROW + r;
        ph1[r] = sh1 + rl * HSTRIDE;
        ph2[r] = sh2 + rl * HSTRIDE;
        int rw = row0 + r;
        rowv[r] = rw;
        int rc = (rw < BATCH) ? rw : (BATCH - 1);
        xr[r] = x + (size_t)rc * SEQ;
    }

    const ulonglong2* sWu2 = reinterpret_cast<const ulonglong2*>(sW);
    const ulonglong2* br1v = reinterpret_cast<const ulonglong2*>(sbr1) + q * 4;
    const ulonglong2* bi2v = reinterpret_cast<const ulonglong2*>(sbi2) + q * 4;
    const ulonglong2* br2v = reinterpret_cast<const ulonglong2*>(sbr2) + q * 4;

    float h1o[NROW][5], h2o[NROW][5];
    #pragma unroll
    for (int r = 0; r < NROW; r++)
        #pragma unroll
        for (int i = 0; i < 5; i++) {
            h1o[r][i] = 0.f; h2o[r][i] = 0.f;
            ph2[r][q * 5 + i] = 0.f;
        }

    // -------- prologue: GRU1(0) (h1 = 0 -> recurrent side = br1) --------
    #pragma unroll
    for (int r = 0; r < NROW; r++) {
        int tok = xr[r][0];
        const float4* pp = reinterpret_cast<const float4*>(g_P + (size_t)tok * 64 + q * 16);
        float4 p0 = pp[0], p1 = pp[1], p2 = pp[2], p3 = pp[3];
        float px[16] = {p0.x,p0.y,p0.z,p0.w, p1.x,p1.y,p1.z,p1.w,
                        p2.x,p2.y,p2.z,p2.w, p3.x,p3.y,p3.z,p3.w};
        float hp[16];
        #pragma unroll
        for (int i = 0; i < 16; i++) hp[i] = sbr1[q * 16 + i];
        gru_gates(px, hp, h1o[r]);   // ho starts at 0
        #pragma unroll
        for (int i = 0; i < 5; i++) ph1[r][q * 5 + i] = h1o[r][i];
    }
    __syncwarp(gmask);

    int tokn[NROW];
    #pragma unroll
    for (int r = 0; r < NROW; r++) tokn[r] = xr[r][1];

    // -------- main loop: iteration t does GRU2(t) and GRU1(t+1) --------
    for (int t = 0; t < SEQ - 1; t++) {
        // prefetch input projections for GRU1(t+1)
        float4 P0[NROW], P1[NROW], P2[NROW], P3[NROW];
        #pragma unroll
        for (int r = 0; r < NROW; r++) {
            const float4* pp = reinterpret_cast<const float4*>(g_P + (size_t)tokn[r] * 64 + q * 16);
            P0[r] = pp[0]; P1[r] = pp[1]; P2[r] = pp[2]; P3[r] = pp[3];
        }
        int t2 = t + 2;
        int i2 = (t2 < SEQ) ? t2 : (SEQ - 1);
        #pragma unroll
        for (int r = 0; r < NROW; r++) tokn[r] = xr[r][i2];

        // ---- pass A: U1 @ h1-old ----
        unsigned long long A[NROW][8];
        #pragma unroll
        for (int j = 0; j < 4; j++) {
            ulonglong2 tb = br1v[j];
            #pragma unroll
            for (int r = 0; r < NROW; r++) { A[r][2*j] = tb.x; A[r][2*j+1] = tb.y; }
        }
        #pragma unroll 5
        for (int k = 0; k < HID; k++) {
            unsigned long long hp0 = pack2(ph1[0][k]);
            unsigned long long hp1 = pack2(ph1[1][k]);
            unsigned long long hp2 = pack2(ph1[2][k]);
            const ulonglong2* wk = sWu2 + k * K_U2;
            #pragma unroll
            for (int j = 0; j < 4; j++) {
                ulonglong2 w = wk[j * 4 + q];
                A[0][2*j]   = fma2(w.x, hp0, A[0][2*j]);
                A[0][2*j+1] = fma2(w.y, hp0, A[0][2*j+1]);
                A[1][2*j]   = fma2(w.x, hp1, A[1][2*j]);
                A[1][2*j+1] = fma2(w.y, hp1, A[1][2*j+1]);
                A[2][2*j]   = fma2(w.x, hp2, A[2][2*j]);
                A[2][2*j+1] = fma2(w.y, hp2, A[2][2*j+1]);
            }
        }
        // GRU1(t+1) gates (h1 shared still holds old values for pass X)
        #pragma unroll
        for (int r = 0; r < NROW; r++) {
            float hp[16];
            #pragma unroll
            for (int j = 0; j < 8; j++) {
                float2 f = unpack2(A[r][j]); hp[2*j] = f.x; hp[2*j+1] = f.y;
            }
            float px[16] = {P0[r].x,P0[r].y,P0[r].z,P0[r].w,
                            P1[r].x,P1[r].y,P1[r].z,P1[r].w,
                            P2[r].x,P2[r].y,P2[r].z,P2[r].w,
                            P3[r].x,P3[r].y,P3[r].z,P3[r].w};
            gru_gates(px, hp, h1o[r]);
        }

        // ---- pass X: W2 @ h1-old ----
        unsigned long long X[NROW][8];
        #pragma unroll
        for (int j = 0; j < 4; j++) {
            ulonglong2 tb = bi2v[j];
            #pragma unroll
            for (int r = 0; r < NROW; r++) { X[r][2*j] = tb.x; X[r][2*j+1] = tb.y; }
        }
        #pragma unroll 5
        for (int k = 0; k < HID; k++) {
            unsigned long long hp0 = pack2(ph1[0][k]);
            unsigned long long hp1 = pack2(ph1[1][k]);
            unsigned long long hp2 = pack2(ph1[2][k]);
            const ulonglong2* wk = sWu2 + k * K_U2 + 16;
            #pragma unroll
            for (int j = 0; j < 4; j++) {
                ulonglong2 w = wk[j * 4 + q];
                X[0][2*j]   = fma2(w.x, hp0, X[0][2*j]);
                X[0][2*j+1] = fma2(w.y, hp0, X[0][2*j+1]);
                X[1][2*j]   = fma2(w.x, hp1, X[1][2*j]);
                X[1][2*j+1] = fma2(w.y, hp1, X[1][2*j+1]);
                X[2][2*j]   = fma2(w.x, hp2, X[2][2*j]);
                X[2][2*j+1] = fma2(w.y, hp2, X[2][2*j+1]);
            }
        }

        // ---- pass H: U2 @ h2-old ----
        unsigned long long Hh[NROW][8];
        #pragma unroll
        for (int j = 0; j < 4; j++) {
            ulonglong2 tb = br2v[j];
            #pragma unroll
            for (int r = 0; r < NROW; r++) { Hh[r][2*j] = tb.x; Hh[r][2*j+1] = tb.y; }
        }
        #pragma unroll 5
        for (int k = 0; k < HID; k++) {
            unsigned long long hp0 = pack2(ph2[0][k]);
            unsigned long long hp1 = pack2(ph2[1][k]);
            unsigned long long hp2 = pack2(ph2[2][k]);
            const ulonglong2* wk = sWu2 + k * K_U2 + 32;
            #pragma unroll
            for (int j = 0; j < 4; j++) {
                ulonglong2 w = wk[j * 4 + q];
                Hh[0][2*j]   = fma2(w.x, hp0, Hh[0][2*j]);
                Hh[0][2*j+1] = fma2(w.y, hp0, Hh[0][2*j+1]);
                Hh[1][2*j]   = fma2(w.x, hp1, Hh[1][2*j]);
                Hh[1][2*j+1] = fma2(w.y, hp1, Hh[1][2*j+1]);
                Hh[2][2*j]   = fma2(w.x, hp2, Hh[2][2*j]);
                Hh[2][2*j+1] = fma2(w.y, hp2, Hh[2][2*j+1]);
            }
        }
        // GRU2(t) gates
        #pragma unroll
        for (int r = 0; r < NROW; r++) {
            float xp[16], hp[16];
            #pragma unroll
            for (int j = 0; j < 8; j++) {
                float2 fx = unpack2(X[r][j]);  xp[2*j] = fx.x; xp[2*j+1] = fx.y;
                float2 fh = unpack2(Hh[r][j]); hp[2*j] = fh.x; hp[2*j+1] = fh.y;
            }
            gru_gates(xp, hp, h2o[r]);
        }

        __syncwarp(gmask);   // all group reads of old h done
        #pragma unroll
        for (int r = 0; r < NROW; r++)
            #pragma unroll
            for (int i = 0; i < 5; i++) {
                ph1[r][q * 5 + i] = h1o[r][i];
                ph2[r][q * 5 + i] = h2o[r][i];
            }
        __syncwarp(gmask);   // new h visible to group
    }

    // -------- epilogue: GRU2(SEQ-1) (pass X + pass H + gates) --------
    {
        unsigned long long X[NROW][8], Hh[NROW][8];
        #pragma unroll
        for (int j = 0; j < 4; j++) {
            ulonglong2 tx = bi2v[j];
            ulonglong2 th = br2v[j];
            #pragma unroll
            for (int r = 0; r < NROW; r++) {
                X[r][2*j] = tx.x;  X[r][2*j+1] = tx.y;
                Hh[r][2*j] = th.x; Hh[r][2*j+1] = th.y;
            }
        }
        #pragma unroll 5
        for (int k = 0; k < HID; k++) {
            unsigned long long a0 = pack2(ph1[0][k]);
            unsigned long long a1 = pack2(ph1[1][k]);
            unsigned long long a2 = pack2(ph1[2][k]);
            unsigned long long c0 = pack2(ph2[0][k]);
            unsigned long long c1 = pack2(ph2[1][k]);
            unsigned long long c2 = pack2(ph2[2][k]);
            const ulonglong2* wk = sWu2 + k * K_U2;
            #pragma unroll
            for (int j = 0; j < 4; j++) {
                ulonglong2 w1 = wk[16 + j * 4 + q];
                X[0][2*j]   = fma2(w1.x, a0, X[0][2*j]);
                X[0][2*j+1] = fma2(w1.y, a0, X[0][2*j+1]);
                X[1][2*j]   = fma2(w1.x, a1, X[1][2*j]);
                X[1][2*j+1] = fma2(w1.y, a1, X[1][2*j+1]);
                X[2][2*j]   = fma2(w1.x, a2, X[2][2*j]);
                X[2][2*j+1] = fma2(w1.y, a2, X[2][2*j+1]);
                ulonglong2 w2 = wk[32 + j * 4 + q];
                Hh[0][2*j]   = fma2(w2.x, c0, Hh[0][2*j]);
                Hh[0][2*j+1] = fma2(w2.y, c0, Hh[0][2*j+1]);
                Hh[1][2*j]   = fma2(w2.x, c1, Hh[1][2*j]);
                Hh[1][2*j+1] = fma2(w2.y, c1, Hh[1][2*j+1]);
                Hh[2][2*j]   = fma2(w2.x, c2, Hh[2][2*j]);
                Hh[2][2*j+1] = fma2(w2.y, c2, Hh[2][2*j+1]);
            }
        }
        #pragma unroll
        for (int r = 0; r < NROW; r++) {
            float xp[16], hp[16];
            #pragma unroll
            for (int j = 0; j < 8; j++) {
                float2 fx = unpack2(X[r][j]);  xp[2*j] = fx.x; xp[2*j+1] = fx.y;
                float2 fh = unpack2(Hh[r][j]); hp[2*j] = fh.x; hp[2*j+1] = fh.y;
            }
            gru_gates(xp, hp, h2o[r]);
        }
        __syncwarp(gmask);
        #pragma unroll
        for (int r = 0; r < NROW; r++)
            #pragma unroll
            for (int i = 0; i < 5; i++)
                ph2[r][q * 5 + i] = h2o[r][i];
        __syncwarp(gmask);
    }

    // -------- dense head (rows guarded; cols q*4..q*4+3) --------
    #pragma unroll
    for (int r = 0; r < NROW; r++) {
        if (rowv[r] >= BATCH) continue;
        float hv[HID];
        #pragma unroll
        for (int k = 0; k < HID; k++) hv[k] = ph2[r][k];
        #pragma unroll
        for (int c = 0; c < 4; c++) {
            int col = q * 4 + c;
            if (col >= NLABEL) break;
            float acc = sbd[col];
            #pragma unroll
            for (int k = 0; k < HID; k++)
                acc = fmaf(hv[k], sWd[k * 16 + col], acc);
            out[(size_t)rowv[r] * NLABEL + col] = acc;
        }
    }
}

// ---------------- launch ----------------
extern "C" void kernel_launch(void* const* d_in, const int* in_sizes, int n_in,
                              void* d_out, int out_size) {
    const int*   x    = (const int*)  d_in[0];
    const float* emb  = (const float*)d_in[1];
    const float* W1   = (const float*)d_in[2];
    const float* U1   = (const float*)d_in[3];
    const float* b1   = (const float*)d_in[4];
    const float* W2   = (const float*)d_in[5];
    const float* U2   = (const float*)d_in[6];
    const float* b2   = (const float*)d_in[7];
    const float* Wd   = (const float*)d_in[8];
    const float* bd   = (const float*)d_in[9];
    float* out = (float*)d_out;

    prep_P_kernel<<<(VOCAB + VPB - 1) / VPB, 256>>>(emb, W1, b1);
    gru_main_kernel<<<(BATCH + RPB - 1) / RPB, BLOCK>>>(x, U1, b1, W2, U2, b2, Wd, bd, out);
}

// round 13
// speedup vs baseline: 1.3102x; 1.2236x over previous
#include <cuda_runtime.h>
#include <cuda_fp16.h>
#include <cstdint>

#define BATCH  8192
#define SEQ    100
#define EMBED  50
#define HID    20
#define NLABEL 15
#define VOCAB  50000

// Precomputed P[v][64] = rearranged(emb_table[v] @ W1 + bi1), owner-major:
// owner q (0..3) gets 16 slots: [0..4]=z cols q*5.., [5..9]=r, [10..14]=h, [15]=pad
__device__ float g_P[VOCAB * 64];

// ---------------- helpers ----------------
__device__ __forceinline__ unsigned long long fma2(unsigned long long a,
                                                   unsigned long long b,
                                                   unsigned long long c) {
    unsigned long long d;
    asm("fma.rn.f32x2 %0, %1, %2, %3;" : "=l"(d) : "l"(a), "l"(b), "l"(c));
    return d;
}
__device__ __forceinline__ unsigned long long pack2(float f) {
    unsigned long long r;
    unsigned int u = __float_as_uint(f);
    asm("mov.b64 %0, {%1, %1};" : "=l"(r) : "r"(u));
    return r;
}
__device__ __forceinline__ float2 unpack2(unsigned long long v) {
    float2 r;
    asm("mov.b64 {%0, %1}, %2;" : "=f"(r.x), "=f"(r.y) : "l"(v));
    return r;
}
// half2 (packed in u32) -> packed f32x2 in u64
__device__ __forceinline__ unsigned long long h2f2(unsigned int h) {
    unsigned long long r;
    asm("{\n\t"
        ".reg .b16 lo, hi;\n\t"
        ".reg .f32 flo, fhi;\n\t"
        "mov.b32 {lo, hi}, %1;\n\t"
        "cvt.f32.f16 flo, lo;\n\t"
        "cvt.f32.f16 fhi, hi;\n\t"
        "mov.b64 %0, {flo, fhi};\n\t"
        "}" : "=l"(r) : "r"(h));
    return r;
}
__device__ __forceinline__ float tanha(float x) {
    float y;
    asm("tanh.approx.f32 %0, %1;" : "=f"(y) : "f"(x));
    return y;
}
// rearranged slot index (0..63) -> original gate column (0..59), or -1 pad
__device__ __forceinline__ int remap_col(int j64) {
    int q = j64 >> 4;
    int jj = j64 & 15;
    if (jj >= 15) return -1;
    int g = jj / 5;
    int l = jj - g * 5;
    return g * HID + q * 5 + l;
}

// ---------------- P precompute ----------------
#define VPB 64
__global__ void __launch_bounds__(256) prep_P_kernel(const float* __restrict__ emb,
                                                     const float* __restrict__ W1,
                                                     const float* __restrict__ b1) {
    __shared__ __align__(16) float W1r[EMBED][64];
    __shared__ float biasr[64];
    __shared__ float embs[VPB][EMBED];
    int tid = threadIdx.x;
    for (int d = tid; d < EMBED * 64; d += 256) {
        int k = d >> 6, j = d & 63;
        int src = remap_col(j);
        W1r[k][j] = (src >= 0) ? W1[k * (3 * HID) + src] : 0.0f;
    }
    if (tid < 64) {
        int src = remap_col(tid);
        biasr[tid] = (src >= 0) ? b1[src] : 0.0f;
    }
    int v0 = blockIdx.x * VPB;
    for (int i = tid; i < VPB * EMBED; i += 256) {
        int vv = i / EMBED, k = i - vv * EMBED;
        int v = v0 + vv;
        embs[vv][k] = (v < VOCAB) ? emb[v * EMBED + k] : 0.0f;
    }
    __syncthreads();
    int d = tid & 63;
    int vbase = tid >> 6;
    #pragma unroll
    for (int i = 0; i < 16; i++) {
        int vl = vbase + 4 * i;
        int v = v0 + vl;
        if (v >= VOCAB) continue;
        float acc = biasr[d];
        #pragma unroll
        for (int k = 0; k < EMBED; k++)
            acc = fmaf(embs[vl][k], W1r[k][d], acc);
        g_P[v * 64 + d] = acc;
    }
}

// ---------------- main fused GRU kernel ----------------
// R7 structure: 4 threads (owners q) x 2 rows per thread, merged single-pass
// k-loop (24 independent f32x2 chains), with weights stored fp16 in shared
// (halved L1 writeback traffic; cvt.f32.f16 on the idle ALU pipe, fp32 accum).
// sW layout (halves): [k][mat][j][q][4]; per-k = 192 halves = 48 uint2;
// mats U1/W2/U2 at uint2 offsets +0/+16/+32 within a k-slice.
#define RPB     56
#define PPB     28          // row-pairs per block
#define BLOCK   112         // 28 pairs * 4 lanes
#define HSTRIDE 21

__global__ void __launch_bounds__(BLOCK) gru_main_kernel(
    const int*   __restrict__ x,
    const float* __restrict__ U1,
    const float* __restrict__ b1,
    const float* __restrict__ W2,
    const float* __restrict__ U2,
    const float* __restrict__ b2,
    const float* __restrict__ Wd,
    const float* __restrict__ bd,
    float*       __restrict__ out) {

    __shared__ __align__(16) __half sW[HID * 192];   // 7680 B
    __shared__ __align__(16) float sbr1[64];
    __shared__ __align__(16) float sbi2[64];
    __shared__ __align__(16) float sbr2[64];
    __shared__ __align__(16) float sWd[HID * 16];
    __shared__ float sbd[16];
    __shared__ __align__(16) float sh1[RPB * HSTRIDE];
    __shared__ __align__(16) float sh2[RPB * HSTRIDE];

    int tid = threadIdx.x;

    // ---- stage interleaved weights (fp16) ----
    for (int d = tid; d < HID * 192; d += BLOCK) {
        int k   = d / 192;
        int rem = d - k * 192;
        int mat = rem >> 6;
        int s64 = rem & 63;            // (j*4+q)*4+c
        int j   = s64 >> 4;
        int q_  = (s64 >> 2) & 3;
        int c   = s64 & 3;
        int jj  = j * 4 + c;
        int src = remap_col(q_ * 16 + jj);
        float v = 0.0f;
        if (src >= 0) {
            int idx = k * (3 * HID) + src;
            v = (mat == 0) ? U1[idx] : (mat == 1) ? W2[idx] : U2[idx];
        }
        sW[d] = __float2half(v);
    }
    if (tid < 64) {
        int src = remap_col(tid);
        float a = 0.0f, bb = 0.0f, c = 0.0f;
        if (src >= 0) {
            a  = b1[3 * HID + src];
            bb = b2[src];
            c  = b2[3 * HID + src];
        }
        sbr1[tid] = a; sbi2[tid] = bb; sbr2[tid] = c;
    }
    for (int d = tid; d < HID * 16; d += BLOCK) {
        int k = d >> 4, j = d & 15;
        sWd[d] = (j < NLABEL) ? Wd[k * NLABEL + j] : 0.0f;
    }
    if (tid < 16) sbd[tid] = (tid < NLABEL) ? bd[tid] : 0.0f;
    __syncthreads();

    int rp = tid >> 2;      // row-pair 0..27
    int q  = tid & 3;
    int rowa = blockIdx.x * RPB + rp * 2;
    if (rowa >= BATCH) return;

    int lane = tid & 31;
    unsigned gmask = 0xFu << (lane & ~3);

    int rla = rp * 2, rlb = rla + 1;
    float* ph1a = sh1 + rla * HSTRIDE;
    float* ph1b = sh1 + rlb * HSTRIDE;
    float* ph2a = sh2 + rla * HSTRIDE;
    float* ph2b = sh2 + rlb * HSTRIDE;

    const int* xa = x + (size_t)rowa * SEQ;
    const int* xb = xa + SEQ;

    const ulonglong2* br1v = reinterpret_cast<const ulonglong2*>(sbr1) + q * 4;
    const ulonglong2* bi2v = reinterpret_cast<const ulonglong2*>(sbi2) + q * 4;
    const ulonglong2* br2v = reinterpret_cast<const ulonglong2*>(sbr2) + q * 4;

    float h1oa[5], h1ob[5], h2oa[5], h2ob[5];
    #pragma unroll
    for (int i = 0; i < 5; i++) {
        h1oa[i] = 0.f; h1ob[i] = 0.f; h2oa[i] = 0.f; h2ob[i] = 0.f;
        ph2a[q * 5 + i] = 0.f;        // GRU2 state starts at 0
        ph2b[q * 5 + i] = 0.f;
    }

    // -------- prologue: GRU1(0) for both rows (h1 = 0 -> mh = br1) --------
    int toka = xa[0], tokb = xb[0];
    {
        const float4* ppa = reinterpret_cast<const float4*>(g_P + (size_t)toka * 64 + q * 16);
        const float4* ppb = reinterpret_cast<const float4*>(g_P + (size_t)tokb * 64 + q * 16);
        float4 a0 = ppa[0], a1 = ppa[1], a2 = ppa[2], a3 = ppa[3];
        float4 b0 = ppb[0], b1_ = ppb[1], b2_ = ppb[2], b3 = ppb[3];
        float pxa[16] = {a0.x,a0.y,a0.z,a0.w, a1.x,a1.y,a1.z,a1.w,
                         a2.x,a2.y,a2.z,a2.w, a3.x,a3.y,a3.z,a3.w};
        float pxb[16] = {b0.x,b0.y,b0.z,b0.w, b1_.x,b1_.y,b1_.z,b1_.w,
                         b2_.x,b2_.y,b2_.z,b2_.w, b3.x,b3.y,b3.z,b3.w};
        #pragma unroll
        for (int i = 0; i < 5; i++) {
            float c0 = sbr1[q * 16 + i];
            float c1 = sbr1[q * 16 + 5 + i];
            float c2 = sbr1[q * 16 + 10 + i];
            {
                float zt = tanha(0.5f * (pxa[i] + c0));
                float r  = 0.5f + 0.5f * tanha(0.5f * (pxa[5 + i] + c1));
                float hh = tanha(pxa[10 + i] + r * c2);
                h1oa[i] = 0.5f * hh - 0.5f * zt * hh;
            }
            {
                float zt = tanha(0.5f * (pxb[i] + c0));
                float r  = 0.5f + 0.5f * tanha(0.5f * (pxb[5 + i] + c1));
                float hh = tanha(pxb[10 + i] + r * c2);
                h1ob[i] = 0.5f * hh - 0.5f * zt * hh;
            }
            ph1a[q * 5 + i] = h1oa[i];
            ph1b[q * 5 + i] = h1ob[i];
        }
        __syncwarp(gmask);
    }

    int tok_na = xa[1], tok_nb = xb[1];

    // -------- main loop: iteration t does GRU2(t) and GRU1(t+1) --------
    for (int t = 0; t < SEQ - 1; t++) {
        unsigned long long Aa[8], Ab[8], Xa[8], Xb[8], Ha[8], Hb[8];
        #pragma unroll
        for (int j = 0; j < 4; j++) {
            ulonglong2 ta = br1v[j]; Aa[2*j] = ta.x; Aa[2*j+1] = ta.y;
                                     Ab[2*j] = ta.x; Ab[2*j+1] = ta.y;
            ulonglong2 tx = bi2v[j]; Xa[2*j] = tx.x; Xa[2*j+1] = tx.y;
                                     Xb[2*j] = tx.x; Xb[2*j+1] = tx.y;
            ulonglong2 th = br2v[j]; Ha[2*j] = th.x; Ha[2*j+1] = th.y;
                                     Hb[2*j] = th.x; Hb[2*j+1] = th.y;
        }
        #pragma unroll 5
        for (int k = 0; k < HID; k++) {
            unsigned long long h1ap = pack2(ph1a[k]);
            unsigned long long h1bp = pack2(ph1b[k]);
            unsigned long long h2ap = pack2(ph2a[k]);
            unsigned long long h2bp = pack2(ph2b[k]);
            const uint2* wk = reinterpret_cast<const uint2*>(sW) + k * 48;
            #pragma unroll
            for (int j = 0; j < 4; j++) {
                uint2 w0 = wk[0 + j * 4 + q];            // U1 (4 halves)
                unsigned long long W00 = h2f2(w0.x), W01 = h2f2(w0.y);
                Aa[2*j]   = fma2(W00, h1ap, Aa[2*j]);
                Aa[2*j+1] = fma2(W01, h1ap, Aa[2*j+1]);
                Ab[2*j]   = fma2(W00, h1bp, Ab[2*j]);
                Ab[2*j+1] = fma2(W01, h1bp, Ab[2*j+1]);
                uint2 w1 = wk[16 + j * 4 + q];           // W2
                unsigned long long W10 = h2f2(w1.x), W11 = h2f2(w1.y);
                Xa[2*j]   = fma2(W10, h1ap, Xa[2*j]);
                Xa[2*j+1] = fma2(W11, h1ap, Xa[2*j+1]);
                Xb[2*j]   = fma2(W10, h1bp, Xb[2*j]);
                Xb[2*j+1] = fma2(W11, h1bp, Xb[2*j+1]);
                uint2 w2 = wk[32 + j * 4 + q];           // U2
                unsigned long long W20 = h2f2(w2.x), W21 = h2f2(w2.y);
                Ha[2*j]   = fma2(W20, h2ap, Ha[2*j]);
                Ha[2*j+1] = fma2(W21, h2ap, Ha[2*j+1]);
                Hb[2*j]   = fma2(W20, h2bp, Hb[2*j]);
                Hb[2*j+1] = fma2(W21, h2bp, Hb[2*j+1]);
            }
        }

        // input projections for GRU1(t+1)
        const float4* ppa = reinterpret_cast<const float4*>(g_P + (size_t)tok_na * 64 + q * 16);
        const float4* ppb = reinterpret_cast<const float4*>(g_P + (size_t)tok_nb * 64 + q * 16);
        float4 pa0 = ppa[0], pa1 = ppa[1], pa2 = ppa[2], pa3 = ppa[3];
        float4 pb0 = ppb[0], pb1 = ppb[1], pb2 = ppb[2], pb3 = ppb[3];
        int t2 = t + 2;
        int idx2 = (t2 < SEQ) ? t2 : (SEQ - 1);
        tok_na = xa[idx2];
        tok_nb = xb[idx2];

        // ---- row a gates ----
        {
            float a[16], bx[16], bh[16];
            #pragma unroll
            for (int j = 0; j < 8; j++) {
                float2 fa = unpack2(Aa[j]); a[2*j]  = fa.x; a[2*j+1]  = fa.y;
                float2 fx = unpack2(Xa[j]); bx[2*j] = fx.x; bx[2*j+1] = fx.y;
                float2 fh = unpack2(Ha[j]); bh[2*j] = fh.x; bh[2*j+1] = fh.y;
            }
            float px[16] = {pa0.x,pa0.y,pa0.z,pa0.w, pa1.x,pa1.y,pa1.z,pa1.w,
                            pa2.x,pa2.y,pa2.z,pa2.w, pa3.x,pa3.y,pa3.z,pa3.w};
            #pragma unroll
            for (int i = 0; i < 5; i++) {
                float zt = tanha(0.5f * (bx[i] + bh[i]));
                float r  = 0.5f + 0.5f * tanha(0.5f * (bx[5+i] + bh[5+i]));
                float hh = tanha(bx[10+i] + r * bh[10+i]);
                float ho = h2oa[i];
                h2oa[i] = 0.5f * (ho + hh) + 0.5f * zt * (ho - hh);
            }
            #pragma unroll
            for (int i = 0; i < 5; i++) {
                float zt = tanha(0.5f * (px[i] + a[i]));
                float r  = 0.5f + 0.5f * tanha(0.5f * (px[5+i] + a[5+i]));
                float hh = tanha(px[10+i] + r * a[10+i]);
                float ho = h1oa[i];
                h1oa[i] = 0.5f * (ho + hh) + 0.5f * zt * (ho - hh);
            }
        }
        // ---- row b gates ----
        {
            float a[16], bx[16], bh[16];
            #pragma unroll
            for (int j = 0; j < 8; j++) {
                float2 fa = unpack2(Ab[j]); a[2*j]  = fa.x; a[2*j+1]  = fa.y;
                float2 fx = unpack2(Xb[j]); bx[2*j] = fx.x; bx[2*j+1] = fx.y;
                float2 fh = unpack2(Hb[j]); bh[2*j] = fh.x; bh[2*j+1] = fh.y;
            }
            float px[16] = {pb0.x,pb0.y,pb0.z,pb0.w, pb1.x,pb1.y,pb1.z,pb1.w,
                            pb2.x,pb2.y,pb2.z,pb2.w, pb3.x,pb3.y,pb3.z,pb3.w};
            #pragma unroll
            for (int i = 0; i < 5; i++) {
                float zt = tanha(0.5f * (bx[i] + bh[i]));
                float r  = 0.5f + 0.5f * tanha(0.5f * (bx[5+i] + bh[5+i]));
                float hh = tanha(bx[10+i] + r * bh[10+i]);
                float ho = h2ob[i];
                h2ob[i] = 0.5f * (ho + hh) + 0.5f * zt * (ho - hh);
            }
            #pragma unroll
            for (int i = 0; i < 5; i++) {
                float zt = tanha(0.5f * (px[i] + a[i]));
                float r  = 0.5f + 0.5f * tanha(0.5f * (px[5+i] + a[5+i]));
                float hh = tanha(px[10+i] + r * a[10+i]);
                float ho = h1ob[i];
                h1ob[i] = 0.5f * (ho + hh) + 0.5f * zt * (ho - hh);
            }
        }

        __syncwarp(gmask);   // all group reads of old h done
        #pragma unroll
        for (int i = 0; i < 5; i++) {
            ph1a[q * 5 + i] = h1oa[i];
            ph1b[q * 5 + i] = h1ob[i];
            ph2a[q * 5 + i] = h2oa[i];
            ph2b[q * 5 + i] = h2ob[i];
        }
        __syncwarp(gmask);   // new h visible to group
    }

    // -------- epilogue: GRU2(SEQ-1) --------
    {
        unsigned long long Xa[8], Xb[8], Ha[8], Hb[8];
        #pragma unroll
        for (int j = 0; j < 4; j++) {
            ulonglong2 tx = bi2v[j]; Xa[2*j] = tx.x; Xa[2*j+1] = tx.y;
                                     Xb[2*j] = tx.x; Xb[2*j+1] = tx.y;
            ulonglong2 th = br2v[j]; Ha[2*j] = th.x; Ha[2*j+1] = th.y;
                                     Hb[2*j] = th.x; Hb[2*j+1] = th.y;
        }
        #pragma unroll 5
        for (int k = 0; k < HID; k++) {
            unsigned long long h1ap = pack2(ph1a[k]);
            unsigned long long h1bp = pack2(ph1b[k]);
            unsigned long long h2ap = pack2(ph2a[k]);
            unsigned long long h2bp = pack2(ph2b[k]);
            const uint2* wk = reinterpret_cast<const uint2*>(sW) + k * 48;
            #pragma unroll
            for (int j = 0; j < 4; j++) {
                uint2 w1 = wk[16 + j * 4 + q];
                unsigned long long W10 = h2f2(w1.x), W11 = h2f2(w1.y);
                Xa[2*j]   = fma2(W10, h1ap, Xa[2*j]);
                Xa[2*j+1] = fma2(W11, h1ap, Xa[2*j+1]);
                Xb[2*j]   = fma2(W10, h1bp, Xb[2*j]);
                Xb[2*j+1] = fma2(W11, h1bp, Xb[2*j+1]);
                uint2 w2 = wk[32 + j * 4 + q];
                unsigned long long W20 = h2f2(w2.x), W21 = h2f2(w2.y);
                Ha[2*j]   = fma2(W20, h2ap, Ha[2*j]);
                Ha[2*j+1] = fma2(W21, h2ap, Ha[2*j+1]);
                Hb[2*j]   = fma2(W20, h2bp, Hb[2*j]);
                Hb[2*j+1] = fma2(W21, h2bp, Hb[2*j+1]);
            }
        }
        {
            float bx[16], bh[16];
            #pragma unroll
            for (int j = 0; j < 8; j++) {
                float2 fx = unpack2(Xa[j]); bx[2*j] = fx.x; bx[2*j+1] = fx.y;
                float2 fh = unpack2(Ha[j]); bh[2*j] = fh.x; bh[2*j+1] = fh.y;
            }
            #pragma unroll
            for (int i = 0; i < 5; i++) {
                float zt = tanha(0.5f * (bx[i] + bh[i]));
                float r  = 0.5f + 0.5f * tanha(0.5f * (bx[5+i] + bh[5+i]));
                float hh = tanha(bx[10+i] + r * bh[10+i]);
                float ho = h2oa[i];
                h2oa[i] = 0.5f * (ho + hh) + 0.5f * zt * (ho - hh);
            }
        }
        {
            float bx[16], bh[16];
            #pragma unroll
            for (int j = 0; j < 8; j++) {
                float2 fx = unpack2(Xb[j]); bx[2*j] = fx.x; bx[2*j+1] = fx.y;
                float2 fh = unpack2(Hb[j]); bh[2*j] = fh.x; bh[2*j+1] = fh.y;
            }
            #pragma unroll
            for (int i = 0; i < 5; i++) {
                float zt = tanha(0.5f * (bx[i] + bh[i]));
                float r  = 0.5f + 0.5f * tanha(0.5f * (bx[5+i] + bh[5+i]));
                float hh = tanha(bx[10+i] + r * bh[10+i]);
                float ho = h2ob[i];
                h2ob[i] = 0.5f * (ho + hh) + 0.5f * zt * (ho - hh);
            }
        }
        __syncwarp(gmask);
        #pragma unroll
        for (int i = 0; i < 5; i++) {
            ph2a[q * 5 + i] = h2oa[i];
            ph2b[q * 5 + i] = h2ob[i];
        }
        __syncwarp(gmask);
    }

    // -------- dense head --------
    {
        float hva[HID], hvb[HID];
        #pragma unroll
        for (int k = 0; k < HID; k++) { hva[k] = ph2a[k]; hvb[k] = ph2b[k]; }
        #pragma unroll
        for (int c = 0; c < 4; c++) {
            int col = q * 4 + c;
            if (col >= NLABEL) break;
            float da = sbd[col], db = sbd[col];
            #pragma unroll
            for (int k = 0; k < HID; k++) {
                float w = sWd[k * 16 + col];
                da = fmaf(hva[k], w, da);
                db = fmaf(hvb[k], w, db);
            }
            out[rowa * NLABEL + col] = da;
            out[(rowa + 1) * NLABEL + col] = db;
        }
    }
}

// ---------------- launch ----------------
extern "C" void kernel_launch(void* const* d_in, const int* in_sizes, int n_in,
                              void* d_out, int out_size) {
    const int*   x    = (const int*)  d_in[0];
    const float* emb  = (const float*)d_in[1];
    const float* W1   = (const float*)d_in[2];
    const float* U1   = (const float*)d_in[3];
    const float* b1   = (const float*)d_in[4];
    const float* W2   = (const float*)d_in[5];
    const float* U2   = (const float*)d_in[6];
    const float* b2   = (const float*)d_in[7];
    const float* Wd   = (const float*)d_in[8];
    const float* bd   = (const float*)d_in[9];
    float* out = (float*)d_out;

    prep_P_kernel<<<(VOCAB + VPB - 1) / VPB, 256>>>(emb, W1, b1);
    gru_main_kernel<<<(BATCH + RPB - 1) / RPB, BLOCK>>>(x, U1, b1, W2, U2, b2, Wd, bd, out);
}